// round 11
// baseline (speedup 1.0000x reference)
#include <cuda_runtime.h>

// Problem constants (fixed by the reference):
//   input : (32, 1, 1024, 1024) float32
//   x_A, y_A, x_B, y_B, ordinal : (32, 100000) int32
//   output: scalar float32 = mean loss over 3.2M points
//
// R11 design (R2-R10 evidence):
//  - traffic pinned ~207 MB (~compulsory floor); DRAM busy 60% in R6 config,
//    but 73.5% shown reachable (R8) -> pressure, not traffic, is the lever
//  - index loads must be R6-style: int4, 32B/lane stride, even/odd pairs
//    issued back-to-back (R8's 64B stride => 2.2x index traffic)
//  - both slices of a thread must hit the SAME image (R9's two-image split
//    doubled the L2 working set => +40 MB)
//  - __ldcg gathers (L2-only), __ldcs indices, deferred compute
#define BB    32
#define HH    1024
#define WW    1024
#define NPTS  100000
#define TOTAL (BB * NPTS)          // 3,200,000
#define HALF  8
#define NTHREADS (TOTAL / 16)      // 200,000 threads, 16 points each
#define TPB   256
#define NBLOCKS ((NTHREADS + TPB - 1) / TPB)   // 782 (last block partial)
#define TPB_PER_B (NPTS / 16)      // 6250 threads per batch
#define GRP_PER_B (NPTS / 4)       // 25000 int4 groups per batch
#define SLICE_GAP (GRP_PER_B / 2)  // 12500 groups between a thread's slices

__device__ double       g_acc   = 0.0;
__device__ unsigned int g_count = 0;

__global__ __launch_bounds__(TPB) void loss_kernel(
    const float* __restrict__ depth,
    const int*   __restrict__ xA,
    const int*   __restrict__ yA,
    const int*   __restrict__ xB,
    const int*   __restrict__ yB,
    const int*   __restrict__ ordv,
    float*       __restrict__ out)
{
    const int t = blockIdx.x * TPB + threadIdx.x;   // 0 .. 200191

    float l = 0.0f;
    if (t < NTHREADS) {
        const int b     = t / TPB_PER_B;            // batch (one per thread)
        const int local = t - b * TPB_PER_B;        // 0 .. 6249
        const int g1    = b * GRP_PER_B + 2 * local;        // slice 1 groups
        const int g2    = g1 + SLICE_GAP;                   // slice 2 groups
        const float* __restrict__ img = depth + (size_t)b * (HH * WW);

        const int4* xA4 = (const int4*)xA;
        const int4* yA4 = (const int4*)yA;
        const int4* xB4 = (const int4*)xB;
        const int4* yB4 = (const int4*)yB;
        const int4* ov4 = (const int4*)ordv;

        // ---- Phase 1: slice-1 indices, then issue 16 gathers ----
        float zA1[HALF], zB1[HALF];
        {
            int4 ax0 = __ldcs(xA4 + g1);
            int4 ax1 = __ldcs(xA4 + g1 + 1);
            int4 ay0 = __ldcs(yA4 + g1);
            int4 ay1 = __ldcs(yA4 + g1 + 1);
            int4 bx0 = __ldcs(xB4 + g1);
            int4 bx1 = __ldcs(xB4 + g1 + 1);
            int4 by0 = __ldcs(yB4 + g1);
            int4 by1 = __ldcs(yB4 + g1 + 1);

            int axv[HALF] = {ax0.x, ax0.y, ax0.z, ax0.w, ax1.x, ax1.y, ax1.z, ax1.w};
            int ayv[HALF] = {ay0.x, ay0.y, ay0.z, ay0.w, ay1.x, ay1.y, ay1.z, ay1.w};
            int bxv[HALF] = {bx0.x, bx0.y, bx0.z, bx0.w, bx1.x, bx1.y, bx1.z, bx1.w};
            int byv[HALF] = {by0.x, by0.y, by0.z, by0.w, by1.x, by1.y, by1.z, by1.w};

            #pragma unroll
            for (int k = 0; k < HALF; k++) {
                zA1[k] = __ldcg(&img[ayv[k] * WW + axv[k]]);
                zB1[k] = __ldcg(&img[byv[k] * WW + bxv[k]]);
            }
        }

        // ---- Phase 2: slice-2 indices (overlap slice-1 gathers), 16 more ----
        float zA2[HALF], zB2[HALF];
        {
            int4 ax0 = __ldcs(xA4 + g2);
            int4 ax1 = __ldcs(xA4 + g2 + 1);
            int4 ay0 = __ldcs(yA4 + g2);
            int4 ay1 = __ldcs(yA4 + g2 + 1);
            int4 bx0 = __ldcs(xB4 + g2);
            int4 bx1 = __ldcs(xB4 + g2 + 1);
            int4 by0 = __ldcs(yB4 + g2);
            int4 by1 = __ldcs(yB4 + g2 + 1);

            int axv[HALF] = {ax0.x, ax0.y, ax0.z, ax0.w, ax1.x, ax1.y, ax1.z, ax1.w};
            int ayv[HALF] = {ay0.x, ay0.y, ay0.z, ay0.w, ay1.x, ay1.y, ay1.z, ay1.w};
            int bxv[HALF] = {bx0.x, bx0.y, bx0.z, bx0.w, bx1.x, bx1.y, bx1.z, bx1.w};
            int byv[HALF] = {by0.x, by0.y, by0.z, by0.w, by1.x, by1.y, by1.z, by1.w};

            #pragma unroll
            for (int k = 0; k < HALF; k++) {
                zA2[k] = __ldcg(&img[ayv[k] * WW + axv[k]]);
                zB2[k] = __ldcg(&img[byv[k] * WW + bxv[k]]);
            }
        }

        // ---- Phase 3: ordinals + deferred compute (all 32 gathers in flight) ----
        int4 o10 = __ldcs(ov4 + g1);
        int4 o11 = __ldcs(ov4 + g1 + 1);
        int4 o20 = __ldcs(ov4 + g2);
        int4 o21 = __ldcs(ov4 + g2 + 1);
        int ov1[HALF] = {o10.x, o10.y, o10.z, o10.w, o11.x, o11.y, o11.z, o11.w};
        int ov2[HALF] = {o20.x, o20.y, o20.z, o20.w, o21.x, o21.y, o21.z, o21.w};

        #pragma unroll
        for (int k = 0; k < HALF; k++) {
            float diff = zA1[k] - zB1[k];
            float gt   = (float)(ov1[k] - 1);
            float mask = fabsf(gt);
            float x    = -gt * diff;
            float sp   = fmaxf(x, 0.0f) + log1pf(expf(-fabsf(x)));
            l += mask * sp + (1.0f - mask) * diff * diff;
        }
        #pragma unroll
        for (int k = 0; k < HALF; k++) {
            float diff = zA2[k] - zB2[k];
            float gt   = (float)(ov2[k] - 1);
            float mask = fabsf(gt);
            float x    = -gt * diff;
            float sp   = fmaxf(x, 0.0f) + log1pf(expf(-fabsf(x)));
            l += mask * sp + (1.0f - mask) * diff * diff;
        }
    }

    // Warp reduction
    #pragma unroll
    for (int off = 16; off > 0; off >>= 1)
        l += __shfl_down_sync(0xffffffffu, l, off);

    __shared__ float warpsums[TPB / 32];
    const int lane = threadIdx.x & 31;
    const int wid  = threadIdx.x >> 5;
    if (lane == 0) warpsums[wid] = l;
    __syncthreads();

    __shared__ bool isLast;
    if (wid == 0) {
        float s = (lane < (TPB / 32)) ? warpsums[lane] : 0.0f;
        #pragma unroll
        for (int off = 4; off > 0; off >>= 1)
            s += __shfl_down_sync(0xffffffffu, s, off);
        if (lane == 0) {
            atomicAdd(&g_acc, (double)s);
            __threadfence();
            unsigned int old = atomicAdd(&g_count, 1u);
            isLast = (old == (unsigned int)(gridDim.x - 1));
        }
    }
    __syncthreads();

    // Last block finalizes and resets state for the next graph replay
    if (isLast && threadIdx.x == 0) {
        __threadfence();
        double acc = *((volatile double*)&g_acc);
        *out = (float)(acc / (double)TOTAL);
        *((volatile double*)&g_acc) = 0.0;
        __threadfence();
        *((volatile unsigned int*)&g_count) = 0u;
    }
}

extern "C" void kernel_launch(void* const* d_in, const int* in_sizes, int n_in,
                              void* d_out, int out_size)
{
    const float* depth = (const float*)d_in[0];
    const int*   xA    = (const int*)d_in[1];
    const int*   yA    = (const int*)d_in[2];
    const int*   xB    = (const int*)d_in[3];
    const int*   yB    = (const int*)d_in[4];
    const int*   ordv  = (const int*)d_in[5];
    float*       out   = (float*)d_out;

    loss_kernel<<<NBLOCKS, TPB>>>(depth, xA, yA, xB, yB, ordv, out);
}

// round 12
// speedup vs baseline: 1.4167x; 1.4167x over previous
#include <cuda_runtime.h>

// Problem constants (fixed by the reference):
//   input : (32, 1, 1024, 1024) float32
//   x_A, y_A, x_B, y_B, ordinal : (32, 100000) int32
//   output: scalar float32 = mean loss over 3.2M points
//
// FINAL / CONVERGED (R2-R11 evidence). R6 configuration — global optimum:
//  - ~207 MB DRAM ~= compulsory floor (64 MB indices + 128 MB unique 64B
//    gather granules + ~15 MB repeat leakage); DRAM busy ~60% = random-64B
//    row-overhead wall
//  - 1563 blocks / 1.32 waves keeps the gather-active footprint at ~24
//    images (~96 MB) < 126 MB L2; every single-wave/PPT=16 variant widened
//    it past L2 and cost 1.2-1.8x traffic (R8, R9, R11)
//  - occupancy (67 vs 88%), MLP (8/16/32 gathers per thread), offset-folding,
//    L2 evict hints on indices: all measured non-binding or harmful
//  - __ldcg gathers (L2-only, no L1 line allocation): -1.2 us, kept
//  - __ldcs warp-consecutive int4 index loads (striding => 2.2x traffic, R8)
//  - single launch: last-block finalize + state reset (graph-replay safe)
#define BB    32
#define HH    1024
#define WW    1024
#define NPTS  100000
#define TOTAL (BB * NPTS)        // 3,200,000
#define PPT   8                  // points per thread (NPTS % 8 == 0)
#define NTHREADS (TOTAL / PPT)   // 400,000
#define TPB   256
#define NBLOCKS ((NTHREADS + TPB - 1) / TPB)  // 1563 (last block partial)

__device__ double       g_acc   = 0.0;
__device__ unsigned int g_count = 0;

__global__ __launch_bounds__(TPB) void loss_kernel(
    const float* __restrict__ depth,
    const int*   __restrict__ xA,
    const int*   __restrict__ yA,
    const int*   __restrict__ xB,
    const int*   __restrict__ yB,
    const int*   __restrict__ ordv,
    float*       __restrict__ out)
{
    const int t = blockIdx.x * TPB + threadIdx.x;   // 0 .. 400127

    float l = 0.0f;
    if (t < NTHREADS) {
        // NPTS % 8 == 0 -> all 8 points of this thread share one batch
        const int b = t / (NPTS / PPT);             // t / 12500
        const float* __restrict__ img = depth + (size_t)b * (HH * WW);

        // Streaming vectorized index loads (touched once; evict-first in L2)
        const int4* xA4 = (const int4*)xA;
        const int4* yA4 = (const int4*)yA;
        const int4* xB4 = (const int4*)xB;
        const int4* yB4 = (const int4*)yB;
        const int4* ov4 = (const int4*)ordv;

        int4 ax0 = __ldcs(xA4 + 2 * t);
        int4 ax1 = __ldcs(xA4 + 2 * t + 1);
        int4 ay0 = __ldcs(yA4 + 2 * t);
        int4 ay1 = __ldcs(yA4 + 2 * t + 1);
        int4 bx0 = __ldcs(xB4 + 2 * t);
        int4 bx1 = __ldcs(xB4 + 2 * t + 1);
        int4 by0 = __ldcs(yB4 + 2 * t);
        int4 by1 = __ldcs(yB4 + 2 * t + 1);
        int4 ov0 = __ldcs(ov4 + 2 * t);
        int4 ov1 = __ldcs(ov4 + 2 * t + 1);

        int axv[PPT] = {ax0.x, ax0.y, ax0.z, ax0.w, ax1.x, ax1.y, ax1.z, ax1.w};
        int ayv[PPT] = {ay0.x, ay0.y, ay0.z, ay0.w, ay1.x, ay1.y, ay1.z, ay1.w};
        int bxv[PPT] = {bx0.x, bx0.y, bx0.z, bx0.w, bx1.x, bx1.y, bx1.z, bx1.w};
        int byv[PPT] = {by0.x, by0.y, by0.z, by0.w, by1.x, by1.y, by1.z, by1.w};
        int ovv[PPT] = {ov0.x, ov0.y, ov0.z, ov0.w, ov1.x, ov1.y, ov1.z, ov1.w};

        // Random 4B gathers: L2-only (.cg) — no L1 line allocation.
        // All 16 issued back-to-back for max MLP.
        float zA[PPT], zB[PPT];
        #pragma unroll
        for (int k = 0; k < PPT; k++) {
            zA[k] = __ldcg(&img[ayv[k] * WW + axv[k]]);
            zB[k] = __ldcg(&img[byv[k] * WW + bxv[k]]);
        }

        #pragma unroll
        for (int k = 0; k < PPT; k++) {
            float diff = zA[k] - zB[k];
            float gt   = (float)(ovv[k] - 1);        // -1, 0, +1
            float mask = fabsf(gt);                  // 0 or 1
            float x    = -gt * diff;
            float sp   = fmaxf(x, 0.0f) + log1pf(expf(-fabsf(x)));
            l += mask * sp + (1.0f - mask) * diff * diff;
        }
    }

    // Warp reduction
    #pragma unroll
    for (int off = 16; off > 0; off >>= 1)
        l += __shfl_down_sync(0xffffffffu, l, off);

    __shared__ float warpsums[TPB / 32];
    const int lane = threadIdx.x & 31;
    const int wid  = threadIdx.x >> 5;
    if (lane == 0) warpsums[wid] = l;
    __syncthreads();

    __shared__ bool isLast;
    if (wid == 0) {
        float s = (lane < (TPB / 32)) ? warpsums[lane] : 0.0f;
        #pragma unroll
        for (int off = 4; off > 0; off >>= 1)
            s += __shfl_down_sync(0xffffffffu, s, off);
        if (lane == 0) {
            atomicAdd(&g_acc, (double)s);
            __threadfence();
            unsigned int old = atomicAdd(&g_count, 1u);
            isLast = (old == (unsigned int)(gridDim.x - 1));
        }
    }
    __syncthreads();

    // Last block finalizes and resets state for the next graph replay
    if (isLast && threadIdx.x == 0) {
        __threadfence();
        double acc = *((volatile double*)&g_acc);
        *out = (float)(acc / (double)TOTAL);
        *((volatile double*)&g_acc) = 0.0;
        __threadfence();
        *((volatile unsigned int*)&g_count) = 0u;
    }
}

extern "C" void kernel_launch(void* const* d_in, const int* in_sizes, int n_in,
                              void* d_out, int out_size)
{
    const float* depth = (const float*)d_in[0];
    const int*   xA    = (const int*)d_in[1];
    const int*   yA    = (const int*)d_in[2];
    const int*   xB    = (const int*)d_in[3];
    const int*   yB    = (const int*)d_in[4];
    const int*   ordv  = (const int*)d_in[5];
    float*       out   = (float*)d_out;

    loss_kernel<<<NBLOCKS, TPB>>>(depth, xA, yA, xB, yB, ordv, out);
}